// round 13
// baseline (speedup 1.0000x reference)
#include <cuda_runtime.h>
#include <cuda_fp16.h>
#include <math.h>

// Cone-beam forward projection, dual-layout fp16 packed volume.
//
// Layout A: g_volA[z][y][x], cell = 8 halves (b0,b1) x (z0,z1) x (x0,x1).
// Layout B: g_volB[z][x][y], cell = 8 halves (b0,b1) x (z0,z1) x (y0,y1).
// fp_kernel picks the layout whose fast axis matches the warp's lane-varying
// world axis -> lane-contiguous 16B-cell gathers at every angle.
// Branchless, software-pipelined sample loop (prefetch i+1's loads before
// i's math) to double per-warp MLP. Interp: x-lerp in half2, y/z-lerp +
// masked accumulate in packed f32x2. Ray split into two half-rays.
// Prep: 2-z-slab smem-tiled pass builds BOTH layouts and zeroes the output.
// vol in: [B=2, Z=96, Y=96, X=96] fp32. out: [B=2, A=48, V=96, U=96] fp32.

#define NZ 96
#define NY 96
#define NX 96
#define NV 96
#define NU 96
#define NA 48
#define NS 96

#define DSO 500.0f
#define DSD 1000.0f
#define DDET 2.0f

#define STEP 1.7320508075688772f
#define T0   416.86156123669393f

#define VOL_N (NZ * NY * NX)     // 884736
#define SROW 96
#define SZ (NX * NY)             // 9216
#define NRAY (NA * NV * NU)      // 442368
#define OUT4 ((2 * NRAY) / 4)    // 221184 float4s
#define NPREPBLK (3 * 3 * 48)    // 432
#define ZPB ((OUT4 + NPREPBLK - 1) / NPREPBLK)   // 512 float4 per prep block

__device__ uint4 g_volA[VOL_N];  // 14.2 MB
__device__ uint4 g_volB[VOL_N];  // 14.2 MB

typedef unsigned long long u64;

static __device__ __forceinline__ unsigned h2u(__half2 h) {
    union { __half2 h; unsigned u; } cvt; cvt.h = h; return cvt.u;
}
static __device__ __forceinline__ __half2 u2h(unsigned u) {
    union { unsigned u; __half2 h; } cvt; cvt.u = u; return cvt.h;
}
static __device__ __forceinline__ u64 pk2(float lo, float hi) {
    u64 r;
    asm("mov.b64 %0, {%1, %2};" : "=l"(r) : "f"(lo), "f"(hi));
    return r;
}
static __device__ __forceinline__ u64 fma2_(u64 a, u64 b, u64 c) {
    u64 d;
    asm("fma.rn.f32x2 %0, %1, %2, %3;" : "=l"(d) : "l"(a), "l"(b), "l"(c));
    return d;
}
static __device__ __forceinline__ u64 lerp2(u64 a, u64 b, u64 f2, u64 nf2) {
    return fma2_(f2, b, fma2_(nf2, a, a));
}

// ---------------------------------------------------------------------------
// Tiled prep (unchanged from R11/R12): builds both layouts, zeroes output.
// grid = (3,3,48), block = 256.
// ---------------------------------------------------------------------------
__global__ void __launch_bounds__(256) prep_tiled(const float* __restrict__ vol,
                                                  float4* __restrict__ outz) {
    __shared__ unsigned s[3][33][35];

    int x0t = blockIdx.x * 32;
    int y0t = blockIdx.y * 32;
    int zb  = blockIdx.z * 2;
    int z2  = min(zb + 2, NZ - 1);

    {
        int blk = (blockIdx.z * gridDim.y + blockIdx.y) * gridDim.x + blockIdx.x;
        int base = blk * ZPB + threadIdx.x;
        const float4 z4 = make_float4(0.f, 0.f, 0.f, 0.f);
        #pragma unroll
        for (int r = 0; r < ZPB / 256; r++) {
            int j = base + r * 256;
            if (j < OUT4) outz[j] = z4;
        }
    }

    const float* b0 = vol;
    const float* b1 = vol + VOL_N;

    int tid = threadIdx.x;

    {
        int yl = tid / 33;
        int xl = tid - yl * 33;
        for (int k = tid; k < 33 * 33; k += 256) {
            int gy = min(y0t + yl, NY - 1);
            int gx = min(x0t + xl, NX - 1);
            int base = gy * NX + gx;
            int i0 = zb * SZ + base;
            int i1 = (zb + 1) * SZ + base;
            int i2 = z2 * SZ + base;
            s[0][yl][xl] = h2u(__floats2half2_rn(b0[i0], b1[i0]));
            s[1][yl][xl] = h2u(__floats2half2_rn(b0[i1], b1[i1]));
            s[2][yl][xl] = h2u(__floats2half2_rn(b0[i2], b1[i2]));
            yl += 7; xl += 25;
            if (xl >= 33) { xl -= 33; yl += 1; }
        }
    }
    __syncthreads();

    int tx = tid & 31;
    int ty = tid >> 5;

    #pragma unroll
    for (int dz = 0; dz < 2; dz++) {
        int z = zb + dz;

        for (int yr = ty; yr < 32; yr += 8) {
            uint4 q;
            q.x = s[dz][yr][tx];
            q.y = s[dz][yr][tx + 1];
            q.z = s[dz + 1][yr][tx];
            q.w = s[dz + 1][yr][tx + 1];
            g_volA[z * SZ + (y0t + yr) * NX + (x0t + tx)] = q;
        }

        for (int xr = ty; xr < 32; xr += 8) {
            uint4 q;
            q.x = s[dz][tx][xr];
            q.y = s[dz][tx + 1][xr];
            q.z = s[dz + 1][tx][xr];
            q.w = s[dz + 1][tx + 1][xr];
            g_volB[z * SZ + (x0t + xr) * NY + (y0t + tx)] = q;
        }
    }
}

// branchless per-sample setup
struct Samp {
    int off;
    float fx, fy, fz, m;
};

static __device__ __forceinline__ Samp mk(float i, float fdx, float fdy, float dz,
                                          float cx, float cy, float cz) {
    float t = fmaf(i + 0.5f, STEP, T0);
    float x = fmaf(fdx, t, cx);
    float y = fmaf(fdy, t, cy);
    float z = fmaf(dz, t, cz);
    Samp sp;
    float mn = fminf(fminf(x, y), z);
    float mx = fmaxf(fmaxf(x, y), z);
    sp.m = ((mn >= 0.0f) & (mx <= 95.0f)) ? 1.0f : 0.0f;
    // clamp -> always in-bounds address
    x = fminf(fmaxf(x, 0.0f), 95.0f);
    y = fminf(fmaxf(y, 0.0f), 95.0f);
    z = fminf(fmaxf(z, 0.0f), 95.0f);
    int x0 = min((int)x, NX - 2);
    int y0 = min((int)y, NY - 2);
    int z0 = min((int)z, NZ - 2);
    sp.fx = x - (float)x0;
    sp.fy = y - (float)y0;
    sp.fz = z - (float)z0;
    sp.off = z0 * SZ + y0 * SROW + x0;
    return sp;
}

__global__ void __launch_bounds__(256, 6) fp_kernel(float* __restrict__ out) {
    int idx = blockIdx.x * blockDim.x + threadIdx.x;   // ray id
    int half = blockIdx.y;                             // 0 or 1
    int u = idx % NU;
    int v = (idx / NU) % NV;
    int a = idx / (NU * NV);

    float theta = (float)a * (6.2831853071795864769f / (float)NA);
    float s = sinf(theta);
    float c = cosf(theta);

    float srcx = DSO * c;
    float srcy = DSO * s;

    float uu = ((float)u - (NU - 1) * 0.5f) * DDET;
    float vv = ((float)v - (NV - 1) * 0.5f) * DDET;

    float px = -(DSD - DSO) * c - uu * s;
    float py = -(DSD - DSO) * s + uu * c;
    float pz = vv;

    float dx = px - srcx;
    float dy = py - srcy;
    float dz = pz;
    float inv = rsqrtf(fmaf(dx, dx, fmaf(dy, dy, dz * dz)));
    dx *= inv; dy *= inv; dz *= inv;

    // ray/box slab test, box = [-47.5, 47.5]^3 world
    const float H = 47.5f;
    float ix_ = 1.0f / dx, iy_ = 1.0f / dy, iz_ = 1.0f / dz;
    float tx1 = (-H - srcx) * ix_, tx2 = (H - srcx) * ix_;
    float ty1 = (-H - srcy) * iy_, ty2 = (H - srcy) * iy_;
    float tz1 = (-H) * iz_,        tz2 = (H) * iz_;
    float tmin = fmaxf(fmaxf(fminf(tx1, tx2), fminf(ty1, ty2)), fminf(tz1, tz2));
    float tmax = fminf(fminf(fmaxf(tx1, tx2), fmaxf(ty1, ty2)), fmaxf(tz1, tz2));

    int i0 = 0, i1 = 0;
    if (tmax > tmin) {
        i0 = max(0, (int)floorf((tmin - T0) / STEP - 0.5f) - 1);
        i1 = min(NS, (int)ceilf((tmax - T0) / STEP - 0.5f) + 2);
    }

    int mid = (i0 + i1) >> 1;
    int sBeg = half ? mid : i0;
    int sEnd = half ? i1 : mid;

    bool useA = fabsf(s) >= fabsf(c);
    const uint4* __restrict__ g = useA ? g_volA : g_volB;

    float fdx = useA ? dx : dy;
    float fdy = useA ? dy : dx;
    float cx = (useA ? srcx : srcy) + 47.5f;
    float cy = (useA ? srcy : srcx) + 47.5f;
    float cz = 47.5f;

    u64 acc = pk2(0.0f, 0.0f);   // (batch0, batch1)

    if (sBeg < sEnd) {
        // ---- software pipeline: loads for sample i in flight during i-1 math
        Samp sp = mk((float)sBeg, fdx, fdy, dz, cx, cy, cz);
        uint4 r0 = __ldg(g + sp.off);
        uint4 r1 = __ldg(g + sp.off + SROW);

        for (int i = sBeg; i < sEnd; i++) {
            // prefetch next (clamped to last valid sample; wasted once at end)
            int inext = min(i + 1, sEnd - 1);
            Samp spn = mk((float)inext, fdx, fdy, dz, cx, cy, cz);
            uint4 n0 = __ldg(g + spn.off);
            uint4 n1 = __ldg(g + spn.off + SROW);

            // ---- math on current sample ----
            __half2 fx2 = __float2half2_rn(sp.fx);
            __half2 q00 = u2h(r0.x), q01 = u2h(r0.y);  // y0: z0
            __half2 q02 = u2h(r0.z), q03 = u2h(r0.w);  // y0: z1
            __half2 q10 = u2h(r1.x), q11 = u2h(r1.y);  // y1: z0
            __half2 q12 = u2h(r1.z), q13 = u2h(r1.w);  // y1: z1

            __half2 xz0y0 = __hfma2(fx2, __hsub2(q01, q00), q00);
            __half2 xz1y0 = __hfma2(fx2, __hsub2(q03, q02), q02);
            __half2 xz0y1 = __hfma2(fx2, __hsub2(q11, q10), q10);
            __half2 xz1y1 = __hfma2(fx2, __hsub2(q13, q12), q12);

            float2 f00 = __half22float2(xz0y0);
            float2 f10 = __half22float2(xz1y0);
            float2 f01 = __half22float2(xz0y1);
            float2 f11 = __half22float2(xz1y1);
            u64 P0y0 = pk2(f00.x, f00.y);
            u64 P1y0 = pk2(f10.x, f10.y);
            u64 P0y1 = pk2(f01.x, f01.y);
            u64 P1y1 = pk2(f11.x, f11.y);

            u64 fy2  = pk2(sp.fy,  sp.fy);
            u64 nfy2 = pk2(-sp.fy, -sp.fy);
            u64 fz2  = pk2(sp.fz,  sp.fz);
            u64 nfz2 = pk2(-sp.fz, -sp.fz);

            u64 z0p = lerp2(P0y0, P0y1, fy2, nfy2);
            u64 z1p = lerp2(P1y0, P1y1, fy2, nfy2);
            u64 r   = lerp2(z0p, z1p, fz2, nfz2);

            u64 m2 = pk2(sp.m, sp.m);
            acc = fma2_(r, m2, acc);     // exact no-op when m = 0

            // rotate
            sp = spn; r0 = n0; r1 = n1;
        }
    }

    float acc0, acc1;
    asm("mov.b64 {%0, %1}, %2;" : "=f"(acc0), "=f"(acc1) : "l"(acc));

    atomicAdd(&out[idx],        acc0 * STEP);
    atomicAdd(&out[idx + NRAY], acc1 * STEP);
}

extern "C" void kernel_launch(void* const* d_in, const int* in_sizes, int n_in,
                              void* d_out, int out_size) {
    const float* vol = (const float*)d_in[0];
    float* out = (float*)d_out;

    {
        dim3 grid(NX / 32, NY / 32, NZ / 2);   // (3,3,48)
        prep_tiled<<<grid, 256>>>(vol, (float4*)out);
    }
    {
        dim3 grid(NRAY / 256, 2);          // (1728, 2)
        fp_kernel<<<grid, 256>>>(out);
    }
}

// round 14
// speedup vs baseline: 1.0707x; 1.0707x over previous
#include <cuda_runtime.h>
#include <cuda_fp16.h>
#include <math.h>

// Cone-beam forward projection, dual-layout fp16 packed volume.
//
// Layout A: g_volA[z][y][x], cell = 8 halves (b0,b1) x (z0,z1) x (x0,x1).
// Layout B: g_volB[z][x][y], cell = 8 halves (b0,b1) x (z0,z1) x (y0,y1).
// fp_kernel picks the layout whose fast axis matches the warp's lane-varying
// world axis -> lane-contiguous 16B-cell gathers at every angle.
// Branchless unrolled sample loop (mask folded into f32x2 accumulate) so
// ptxas can batch loads across iterations. Interp: x-lerp in half2,
// y/z-lerp + masked accumulate in packed f32x2. Ray split into two
// half-rays (gridDim.y=2), combined via atomicAdd (2 adds -> deterministic).
// Prep: 2-z-slab smem-tiled pass builds BOTH layouts and zeroes the output.
// vol in: [B=2, Z=96, Y=96, X=96] fp32. out: [B=2, A=48, V=96, U=96] fp32.

#define NZ 96
#define NY 96
#define NX 96
#define NV 96
#define NU 96
#define NA 48
#define NS 96

#define DSO 500.0f
#define DSD 1000.0f
#define DDET 2.0f

#define STEP 1.7320508075688772f
#define T0   416.86156123669393f

#define VOL_N (NZ * NY * NX)     // 884736
#define SROW 96
#define SZ (NX * NY)             // 9216
#define NRAY (NA * NV * NU)      // 442368
#define OUT4 ((2 * NRAY) / 4)    // 221184 float4s
#define NPREPBLK (3 * 3 * 48)    // 432
#define ZPB ((OUT4 + NPREPBLK - 1) / NPREPBLK)   // 512 float4 per prep block

__device__ uint4 g_volA[VOL_N];  // 14.2 MB
__device__ uint4 g_volB[VOL_N];  // 14.2 MB

typedef unsigned long long u64;

static __device__ __forceinline__ unsigned h2u(__half2 h) {
    union { __half2 h; unsigned u; } cvt; cvt.h = h; return cvt.u;
}
static __device__ __forceinline__ __half2 u2h(unsigned u) {
    union { unsigned u; __half2 h; } cvt; cvt.u = u; return cvt.h;
}
static __device__ __forceinline__ u64 pk2(float lo, float hi) {
    u64 r;
    asm("mov.b64 %0, {%1, %2};" : "=l"(r) : "f"(lo), "f"(hi));
    return r;
}
static __device__ __forceinline__ u64 fma2_(u64 a, u64 b, u64 c) {
    u64 d;
    asm("fma.rn.f32x2 %0, %1, %2, %3;" : "=l"(d) : "l"(a), "l"(b), "l"(c));
    return d;
}
static __device__ __forceinline__ u64 lerp2(u64 a, u64 b, u64 f2, u64 nf2) {
    return fma2_(f2, b, fma2_(nf2, a, a));
}

// ---------------------------------------------------------------------------
// Tiled prep (unchanged): builds both layouts, zeroes output.
// grid = (3,3,48), block = 256.
// ---------------------------------------------------------------------------
__global__ void __launch_bounds__(256) prep_tiled(const float* __restrict__ vol,
                                                  float4* __restrict__ outz) {
    __shared__ unsigned s[3][33][35];

    int x0t = blockIdx.x * 32;
    int y0t = blockIdx.y * 32;
    int zb  = blockIdx.z * 2;
    int z2  = min(zb + 2, NZ - 1);

    {
        int blk = (blockIdx.z * gridDim.y + blockIdx.y) * gridDim.x + blockIdx.x;
        int base = blk * ZPB + threadIdx.x;
        const float4 z4 = make_float4(0.f, 0.f, 0.f, 0.f);
        #pragma unroll
        for (int r = 0; r < ZPB / 256; r++) {
            int j = base + r * 256;
            if (j < OUT4) outz[j] = z4;
        }
    }

    const float* b0 = vol;
    const float* b1 = vol + VOL_N;

    int tid = threadIdx.x;

    {
        int yl = tid / 33;
        int xl = tid - yl * 33;
        for (int k = tid; k < 33 * 33; k += 256) {
            int gy = min(y0t + yl, NY - 1);
            int gx = min(x0t + xl, NX - 1);
            int base = gy * NX + gx;
            int i0 = zb * SZ + base;
            int i1 = (zb + 1) * SZ + base;
            int i2 = z2 * SZ + base;
            s[0][yl][xl] = h2u(__floats2half2_rn(b0[i0], b1[i0]));
            s[1][yl][xl] = h2u(__floats2half2_rn(b0[i1], b1[i1]));
            s[2][yl][xl] = h2u(__floats2half2_rn(b0[i2], b1[i2]));
            yl += 7; xl += 25;
            if (xl >= 33) { xl -= 33; yl += 1; }
        }
    }
    __syncthreads();

    int tx = tid & 31;
    int ty = tid >> 5;

    #pragma unroll
    for (int dz = 0; dz < 2; dz++) {
        int z = zb + dz;

        for (int yr = ty; yr < 32; yr += 8) {
            uint4 q;
            q.x = s[dz][yr][tx];
            q.y = s[dz][yr][tx + 1];
            q.z = s[dz + 1][yr][tx];
            q.w = s[dz + 1][yr][tx + 1];
            g_volA[z * SZ + (y0t + yr) * NX + (x0t + tx)] = q;
        }

        for (int xr = ty; xr < 32; xr += 8) {
            uint4 q;
            q.x = s[dz][tx][xr];
            q.y = s[dz][tx + 1][xr];
            q.z = s[dz + 1][tx][xr];
            q.w = s[dz + 1][tx + 1][xr];
            g_volB[z * SZ + (x0t + xr) * NY + (y0t + tx)] = q;
        }
    }
}

__global__ void __launch_bounds__(256) fp_kernel(float* __restrict__ out) {
    int idx = blockIdx.x * blockDim.x + threadIdx.x;   // ray id
    int half = blockIdx.y;                             // 0 or 1
    int u = idx % NU;
    int v = (idx / NU) % NV;
    int a = idx / (NU * NV);

    float theta = (float)a * (6.2831853071795864769f / (float)NA);
    float s = sinf(theta);
    float c = cosf(theta);

    float srcx = DSO * c;
    float srcy = DSO * s;

    float uu = ((float)u - (NU - 1) * 0.5f) * DDET;
    float vv = ((float)v - (NV - 1) * 0.5f) * DDET;

    float px = -(DSD - DSO) * c - uu * s;
    float py = -(DSD - DSO) * s + uu * c;
    float pz = vv;

    float dx = px - srcx;
    float dy = py - srcy;
    float dz = pz;
    float inv = rsqrtf(fmaf(dx, dx, fmaf(dy, dy, dz * dz)));
    dx *= inv; dy *= inv; dz *= inv;

    // ray/box slab test, box = [-47.5, 47.5]^3 world
    const float H = 47.5f;
    float ix_ = 1.0f / dx, iy_ = 1.0f / dy, iz_ = 1.0f / dz;
    float tx1 = (-H - srcx) * ix_, tx2 = (H - srcx) * ix_;
    float ty1 = (-H - srcy) * iy_, ty2 = (H - srcy) * iy_;
    float tz1 = (-H) * iz_,        tz2 = (H) * iz_;
    float tmin = fmaxf(fmaxf(fminf(tx1, tx2), fminf(ty1, ty2)), fminf(tz1, tz2));
    float tmax = fminf(fminf(fmaxf(tx1, tx2), fmaxf(ty1, ty2)), fmaxf(tz1, tz2));

    int i0 = 0, i1 = 0;
    if (tmax > tmin) {
        i0 = max(0, (int)floorf((tmin - T0) / STEP - 0.5f) - 1);
        i1 = min(NS, (int)ceilf((tmax - T0) / STEP - 0.5f) + 2);
    }

    int mid = (i0 + i1) >> 1;
    int sBeg = half ? mid : i0;
    int sEnd = half ? i1 : mid;

    bool useA = fabsf(s) >= fabsf(c);
    const uint4* __restrict__ g = useA ? g_volA : g_volB;

    float fdx = useA ? dx : dy;
    float fdy = useA ? dy : dx;
    float cx = (useA ? srcx : srcy) + 47.5f;
    float cy = (useA ? srcy : srcx) + 47.5f;
    float cz = 47.5f;

    u64 acc = pk2(0.0f, 0.0f);   // (batch0, batch1)

    #pragma unroll 4
    for (int i = sBeg; i < sEnd; i++) {
        float t = fmaf((float)i + 0.5f, STEP, T0);
        float x = fmaf(fdx, t, cx);   // fast axis
        float y = fmaf(fdy, t, cy);   // slow axis
        float z = fmaf(dz, t, cz);

        // mask, then clamp -> always-in-bounds address (branchless body)
        float mn = fminf(fminf(x, y), z);
        float mx = fmaxf(fmaxf(x, y), z);
        float m = ((mn >= 0.0f) & (mx <= 95.0f)) ? 1.0f : 0.0f;

        x = fminf(fmaxf(x, 0.0f), 95.0f);
        y = fminf(fmaxf(y, 0.0f), 95.0f);
        z = fminf(fmaxf(z, 0.0f), 95.0f);
        int x0 = min((int)x, NX - 2);
        int y0 = min((int)y, NY - 2);
        int z0 = min((int)z, NZ - 2);
        float fx = x - (float)x0;
        float fy = y - (float)y0;
        float fz = z - (float)z0;

        const uint4* p = g + (z0 * SZ + y0 * SROW + x0);
        uint4 r0 = __ldg(p);          // slow row 0: (z0f0, z0f1, z1f0, z1f1)
        uint4 r1 = __ldg(p + SROW);   // slow row 1

        // ---- x-lerp in half2 (batch pair in lanes), 4 independent ----
        __half2 fx2 = __float2half2_rn(fx);
        __half2 q00 = u2h(r0.x), q01 = u2h(r0.y);  // y0: z0
        __half2 q02 = u2h(r0.z), q03 = u2h(r0.w);  // y0: z1
        __half2 q10 = u2h(r1.x), q11 = u2h(r1.y);  // y1: z0
        __half2 q12 = u2h(r1.z), q13 = u2h(r1.w);  // y1: z1

        __half2 xz0y0 = __hfma2(fx2, __hsub2(q01, q00), q00);
        __half2 xz1y0 = __hfma2(fx2, __hsub2(q03, q02), q02);
        __half2 xz0y1 = __hfma2(fx2, __hsub2(q11, q10), q10);
        __half2 xz1y1 = __hfma2(fx2, __hsub2(q13, q12), q12);

        // ---- convert 4 survivors, pack into f32x2 pairs ----
        float2 f00 = __half22float2(xz0y0);
        float2 f10 = __half22float2(xz1y0);
        float2 f01 = __half22float2(xz0y1);
        float2 f11 = __half22float2(xz1y1);
        u64 P0y0 = pk2(f00.x, f00.y);
        u64 P1y0 = pk2(f10.x, f10.y);
        u64 P0y1 = pk2(f01.x, f01.y);
        u64 P1y1 = pk2(f11.x, f11.y);

        // ---- y-lerp, z-lerp, masked accumulate in f32x2 ----
        u64 fy2  = pk2(fy,  fy);
        u64 nfy2 = pk2(-fy, -fy);
        u64 fz2  = pk2(fz,  fz);
        u64 nfz2 = pk2(-fz, -fz);

        u64 z0p = lerp2(P0y0, P0y1, fy2, nfy2);
        u64 z1p = lerp2(P1y0, P1y1, fy2, nfy2);
        u64 r   = lerp2(z0p, z1p, fz2, nfz2);

        u64 m2 = pk2(m, m);
        acc = fma2_(r, m2, acc);     // exact no-op when m = 0
    }

    float acc0, acc1;
    asm("mov.b64 {%0, %1}, %2;" : "=f"(acc0), "=f"(acc1) : "l"(acc));

    atomicAdd(&out[idx],        acc0 * STEP);
    atomicAdd(&out[idx + NRAY], acc1 * STEP);
}

extern "C" void kernel_launch(void* const* d_in, const int* in_sizes, int n_in,
                              void* d_out, int out_size) {
    const float* vol = (const float*)d_in[0];
    float* out = (float*)d_out;

    {
        dim3 grid(NX / 32, NY / 32, NZ / 2);   // (3,3,48)
        prep_tiled<<<grid, 256>>>(vol, (float4*)out);
    }
    {
        dim3 grid(NRAY / 256, 2);          // (1728, 2)
        fp_kernel<<<grid, 256>>>(out);
    }
}

// round 15
// speedup vs baseline: 1.1213x; 1.0472x over previous
#include <cuda_runtime.h>
#include <cuda_fp16.h>
#include <math.h>

// Cone-beam forward projection, dual-layout fp16 packed volume.
//
// Layout A: g_volA[z][y][x], cell = 8 halves (b0,b1) x (z0,z1) x (x0,x1).
// Layout B: g_volB[z][x][y], cell = 8 halves (b0,b1) x (z0,z1) x (y0,y1).
// fp_kernel picks the layout whose fast axis matches the warp's lane-varying
// world axis -> lane-contiguous 16B-cell gathers at every angle.
// Interp: x-lerp AND y-lerp in half2 (batch pair in lanes), z-lerp +
// accumulate in packed f32x2 with hoisted +/-1 constants. Branchy body.
// Ray split into two half-rays (gridDim.y=2); partials combined via
// atomicAdd (exactly 2 adds/address -> deterministic, fp add commutative).
// Prep: 2-z-slab smem-tiled pass builds BOTH layouts and zeroes the output.
// vol in: [B=2, Z=96, Y=96, X=96] fp32. out: [B=2, A=48, V=96, U=96] fp32.

#define NZ 96
#define NY 96
#define NX 96
#define NV 96
#define NU 96
#define NA 48
#define NS 96

#define DSO 500.0f
#define DSD 1000.0f
#define DDET 2.0f

#define STEP 1.7320508075688772f
#define T0   416.86156123669393f

#define VOL_N (NZ * NY * NX)     // 884736
#define SROW 96
#define SZ (NX * NY)             // 9216
#define NRAY (NA * NV * NU)      // 442368
#define OUT4 ((2 * NRAY) / 4)    // 221184 float4s
#define NPREPBLK (3 * 3 * 48)    // 432
#define ZPB ((OUT4 + NPREPBLK - 1) / NPREPBLK)   // 512 float4 per prep block

__device__ uint4 g_volA[VOL_N];  // 14.2 MB
__device__ uint4 g_volB[VOL_N];  // 14.2 MB

typedef unsigned long long u64;

static __device__ __forceinline__ unsigned h2u(__half2 h) {
    union { __half2 h; unsigned u; } cvt; cvt.h = h; return cvt.u;
}
static __device__ __forceinline__ __half2 u2h(unsigned u) {
    union { unsigned u; __half2 h; } cvt; cvt.u = u; return cvt.h;
}
static __device__ __forceinline__ u64 pk2(float lo, float hi) {
    u64 r;
    asm("mov.b64 %0, {%1, %2};" : "=l"(r) : "f"(lo), "f"(hi));
    return r;
}
static __device__ __forceinline__ u64 fma2_(u64 a, u64 b, u64 c) {
    u64 d;
    asm("fma.rn.f32x2 %0, %1, %2, %3;" : "=l"(d) : "l"(a), "l"(b), "l"(c));
    return d;
}

// ---------------------------------------------------------------------------
// Tiled prep (unchanged): builds both layouts, zeroes output.
// grid = (3,3,48), block = 256.
// ---------------------------------------------------------------------------
__global__ void __launch_bounds__(256) prep_tiled(const float* __restrict__ vol,
                                                  float4* __restrict__ outz) {
    __shared__ unsigned s[3][33][35];

    int x0t = blockIdx.x * 32;
    int y0t = blockIdx.y * 32;
    int zb  = blockIdx.z * 2;
    int z2  = min(zb + 2, NZ - 1);

    {
        int blk = (blockIdx.z * gridDim.y + blockIdx.y) * gridDim.x + blockIdx.x;
        int base = blk * ZPB + threadIdx.x;
        const float4 z4 = make_float4(0.f, 0.f, 0.f, 0.f);
        #pragma unroll
        for (int r = 0; r < ZPB / 256; r++) {
            int j = base + r * 256;
            if (j < OUT4) outz[j] = z4;
        }
    }

    const float* b0 = vol;
    const float* b1 = vol + VOL_N;

    int tid = threadIdx.x;

    {
        int yl = tid / 33;
        int xl = tid - yl * 33;
        for (int k = tid; k < 33 * 33; k += 256) {
            int gy = min(y0t + yl, NY - 1);
            int gx = min(x0t + xl, NX - 1);
            int base = gy * NX + gx;
            int i0 = zb * SZ + base;
            int i1 = (zb + 1) * SZ + base;
            int i2 = z2 * SZ + base;
            s[0][yl][xl] = h2u(__floats2half2_rn(b0[i0], b1[i0]));
            s[1][yl][xl] = h2u(__floats2half2_rn(b0[i1], b1[i1]));
            s[2][yl][xl] = h2u(__floats2half2_rn(b0[i2], b1[i2]));
            yl += 7; xl += 25;
            if (xl >= 33) { xl -= 33; yl += 1; }
        }
    }
    __syncthreads();

    int tx = tid & 31;
    int ty = tid >> 5;

    #pragma unroll
    for (int dz = 0; dz < 2; dz++) {
        int z = zb + dz;

        for (int yr = ty; yr < 32; yr += 8) {
            uint4 q;
            q.x = s[dz][yr][tx];
            q.y = s[dz][yr][tx + 1];
            q.z = s[dz + 1][yr][tx];
            q.w = s[dz + 1][yr][tx + 1];
            g_volA[z * SZ + (y0t + yr) * NX + (x0t + tx)] = q;
        }

        for (int xr = ty; xr < 32; xr += 8) {
            uint4 q;
            q.x = s[dz][tx][xr];
            q.y = s[dz][tx + 1][xr];
            q.z = s[dz + 1][tx][xr];
            q.w = s[dz + 1][tx + 1][xr];
            g_volB[z * SZ + (x0t + xr) * NY + (y0t + tx)] = q;
        }
    }
}

__global__ void __launch_bounds__(256) fp_kernel(float* __restrict__ out) {
    int idx = blockIdx.x * blockDim.x + threadIdx.x;   // ray id
    int half = blockIdx.y;                             // 0 or 1
    int u = idx % NU;
    int v = (idx / NU) % NV;
    int a = idx / (NU * NV);

    float theta = (float)a * (6.2831853071795864769f / (float)NA);
    float s = sinf(theta);
    float c = cosf(theta);

    float srcx = DSO * c;
    float srcy = DSO * s;

    float uu = ((float)u - (NU - 1) * 0.5f) * DDET;
    float vv = ((float)v - (NV - 1) * 0.5f) * DDET;

    float px = -(DSD - DSO) * c - uu * s;
    float py = -(DSD - DSO) * s + uu * c;
    float pz = vv;

    float dx = px - srcx;
    float dy = py - srcy;
    float dz = pz;
    float inv = rsqrtf(fmaf(dx, dx, fmaf(dy, dy, dz * dz)));
    dx *= inv; dy *= inv; dz *= inv;

    // ray/box slab test, box = [-47.5, 47.5]^3 world
    const float H = 47.5f;
    float ix_ = 1.0f / dx, iy_ = 1.0f / dy, iz_ = 1.0f / dz;
    float tx1 = (-H - srcx) * ix_, tx2 = (H - srcx) * ix_;
    float ty1 = (-H - srcy) * iy_, ty2 = (H - srcy) * iy_;
    float tz1 = (-H) * iz_,        tz2 = (H) * iz_;
    float tmin = fmaxf(fmaxf(fminf(tx1, tx2), fminf(ty1, ty2)), fminf(tz1, tz2));
    float tmax = fminf(fminf(fmaxf(tx1, tx2), fmaxf(ty1, ty2)), fmaxf(tz1, tz2));

    int i0 = 0, i1 = 0;
    if (tmax > tmin) {
        i0 = max(0, (int)floorf((tmin - T0) / STEP - 0.5f) - 1);
        i1 = min(NS, (int)ceilf((tmax - T0) / STEP - 0.5f) + 2);
    }

    int mid = (i0 + i1) >> 1;
    int sBeg = half ? mid : i0;
    int sEnd = half ? i1 : mid;

    bool useA = fabsf(s) >= fabsf(c);
    const uint4* __restrict__ g = useA ? g_volA : g_volB;

    float fdx = useA ? dx : dy;
    float fdy = useA ? dy : dx;
    float cx = (useA ? srcx : srcy) + 47.5f;
    float cy = (useA ? srcy : srcx) + 47.5f;
    float cz = 47.5f;

    u64 acc = pk2(0.0f, 0.0f);        // (batch0, batch1)
    const u64 one2  = pk2(1.0f, 1.0f);
    const u64 neg12 = pk2(-1.0f, -1.0f);

    #pragma unroll 4
    for (int i = sBeg; i < sEnd; i++) {
        float t = fmaf((float)i + 0.5f, STEP, T0);
        float x = fmaf(fdx, t, cx);   // fast axis
        float y = fmaf(fdy, t, cy);   // slow axis
        float z = fmaf(dz, t, cz);

        float mn = fminf(fminf(x, y), z);
        float mx = fmaxf(fmaxf(x, y), z);
        if ((mn >= 0.0f) & (mx <= 95.0f)) {
            int x0 = min((int)x, NX - 2);
            int y0 = min((int)y, NY - 2);
            int z0 = min((int)z, NZ - 2);
            float fx = x - (float)x0;
            float fy = y - (float)y0;
            float fz = z - (float)z0;

            const uint4* p = g + (z0 * SZ + y0 * SROW + x0);
            uint4 r0 = __ldg(p);          // slow row 0: (z0f0, z0f1, z1f0, z1f1)
            uint4 r1 = __ldg(p + SROW);   // slow row 1

            // ---- x-lerp in half2 (batch pair in lanes), 4 independent ----
            __half2 fx2 = __float2half2_rn(fx);
            __half2 q00 = u2h(r0.x), q01 = u2h(r0.y);  // y0: z0
            __half2 q02 = u2h(r0.z), q03 = u2h(r0.w);  // y0: z1
            __half2 q10 = u2h(r1.x), q11 = u2h(r1.y);  // y1: z0
            __half2 q12 = u2h(r1.z), q13 = u2h(r1.w);  // y1: z1

            __half2 xz0y0 = __hfma2(fx2, __hsub2(q01, q00), q00);
            __half2 xz1y0 = __hfma2(fx2, __hsub2(q03, q02), q02);
            __half2 xz0y1 = __hfma2(fx2, __hsub2(q11, q10), q10);
            __half2 xz1y1 = __hfma2(fx2, __hsub2(q13, q12), q12);

            // ---- y-lerp in half2 (R8-validated numerics) ----
            __half2 fy2 = __float2half2_rn(fy);
            __half2 yz0 = __hfma2(fy2, __hsub2(xz0y1, xz0y0), xz0y0);
            __half2 yz1 = __hfma2(fy2, __hsub2(xz1y1, xz1y0), xz1y0);

            // ---- convert 2 survivors, z-lerp + accumulate in f32x2 ----
            float2 f0 = __half22float2(yz0);
            float2 f1 = __half22float2(yz1);
            u64 Z0 = pk2(f0.x, f0.y);
            u64 Z1 = pk2(f1.x, f1.y);
            u64 fz2 = pk2(fz, fz);

            u64 d = fma2_(neg12, Z0, Z1);          // Z1 - Z0
            acc = fma2_(fz2, d, fma2_(one2, Z0, acc));  // acc + Z0 + fz*(Z1-Z0)
        }
    }

    float acc0, acc1;
    asm("mov.b64 {%0, %1}, %2;" : "=f"(acc0), "=f"(acc1) : "l"(acc));

    atomicAdd(&out[idx],        acc0 * STEP);
    atomicAdd(&out[idx + NRAY], acc1 * STEP);
}

extern "C" void kernel_launch(void* const* d_in, const int* in_sizes, int n_in,
                              void* d_out, int out_size) {
    const float* vol = (const float*)d_in[0];
    float* out = (float*)d_out;

    {
        dim3 grid(NX / 32, NY / 32, NZ / 2);   // (3,3,48)
        prep_tiled<<<grid, 256>>>(vol, (float4*)out);
    }
    {
        dim3 grid(NRAY / 256, 2);          // (1728, 2)
        fp_kernel<<<grid, 256>>>(out);
    }
}